// round 3
// baseline (speedup 1.0000x reference)
#include <cuda_runtime.h>
#include <math.h>

#define NN 262144
#define LL 128
#define LOG_L 7
#define CC (NN / LL)      // 2048 chunks
#define GG 64             // 64 groups of 32 chunks
#define MM 2048
#define GRAV 9.81007f

struct S12 { float4 dq; float Ax,Ay,Az,Px,Py,Pz,T,G; };
struct DS  { float4 dq; double Ax,Ay,Az,Px,Py,Pz,T,G; };

__device__ float4 g_dq[NN];     // per-step exp_so3 quaternion
__device__ float4 g_adt[NN];    // a.xyz (bias-corrected), dt
__device__ float4 g_s0[CC];     // chunk summary: dq
__device__ float4 g_s1[CC];     // Ax,Ay,Az,T
__device__ float4 g_s2[CC];     // Px,Py,Pz,G
__device__ DS g_incl[CC];       // within-group inclusive scans (double)
__device__ DS g_gt[GG];         // group totals
__device__ DS g_gp[GG];         // group exclusive prefixes
__device__ float4 g_sq[CC];     // chunk-start rotation (world)
__device__ double g_sv[3 * CC];
__device__ double g_sp[3 * CC];
__device__ double g_part[2 * MM];

// ---------------- quaternion helpers ----------------
__device__ __forceinline__ float4 qmul4(float4 q, float4 r) {
    return make_float4(
        q.w*r.x + q.x*r.w + q.y*r.z - q.z*r.y,
        q.w*r.y - q.x*r.z + q.y*r.w + q.z*r.x,
        q.w*r.z + q.x*r.y - q.y*r.x + q.z*r.w,
        q.w*r.w - q.x*r.x - q.y*r.y - q.z*r.z);
}
__device__ __forceinline__ float4 qnorm4(float4 q) {
    float n = rsqrtf(q.x*q.x + q.y*q.y + q.z*q.z + q.w*q.w);
    return make_float4(q.x*n, q.y*n, q.z*n, q.w*n);
}
__device__ __forceinline__ float3 qrot3(float4 q, float3 v) {
    float tx = 2.0f*(q.y*v.z - q.z*v.y);
    float ty = 2.0f*(q.z*v.x - q.x*v.z);
    float tz = 2.0f*(q.x*v.y - q.y*v.x);
    return make_float3(
        v.x + q.w*tx + (q.y*tz - q.z*ty),
        v.y + q.w*ty + (q.z*tx - q.x*tz),
        v.z + q.w*tz + (q.x*ty - q.y*tx));
}
__device__ __forceinline__ void qrotd(float4 qf, double vx, double vy, double vz,
                                      double& ox, double& oy, double& oz) {
    double qx = qf.x, qy = qf.y, qz = qf.z, qw = qf.w;
    double tx = 2.0*(qy*vz - qz*vy);
    double ty = 2.0*(qz*vx - qx*vz);
    double tz = 2.0*(qx*vy - qy*vx);
    ox = vx + qw*tx + (qy*tz - qz*ty);
    oy = vy + qw*ty + (qz*tx - qx*tz);
    oz = vz + qw*tz + (qx*ty - qy*tx);
}

// ---------------- float summary algebra ----------------
__device__ __forceinline__ S12 sident() {
    S12 s; s.dq = make_float4(0.f,0.f,0.f,1.f);
    s.Ax=s.Ay=s.Az=s.Px=s.Py=s.Pz=0.f; s.T=s.G=0.f; return s;
}
__device__ __forceinline__ S12 scomb(const S12& a, const S12& b) {
    S12 o;
    o.T = a.T + b.T;
    o.G = a.G + a.T*b.T + b.G;
    float3 rA = qrot3(a.dq, make_float3(b.Ax, b.Ay, b.Az));
    o.Ax = a.Ax + rA.x;  o.Ay = a.Ay + rA.y;  o.Az = a.Az + rA.z;
    float3 rP = qrot3(a.dq, make_float3(b.Px, b.Py, b.Pz));
    o.Px = a.Px + a.Ax*b.T + rP.x;
    o.Py = a.Py + a.Ay*b.T + rP.y;
    o.Pz = a.Pz + a.Az*b.T + rP.z;
    o.dq = qmul4(a.dq, b.dq);
    return o;
}
#define WALL 0xffffffffu
__device__ __forceinline__ S12 shfl_down_S(const S12& s, int off) {
    S12 r;
    r.dq.x = __shfl_down_sync(WALL, s.dq.x, off);
    r.dq.y = __shfl_down_sync(WALL, s.dq.y, off);
    r.dq.z = __shfl_down_sync(WALL, s.dq.z, off);
    r.dq.w = __shfl_down_sync(WALL, s.dq.w, off);
    r.Ax = __shfl_down_sync(WALL, s.Ax, off);
    r.Ay = __shfl_down_sync(WALL, s.Ay, off);
    r.Az = __shfl_down_sync(WALL, s.Az, off);
    r.Px = __shfl_down_sync(WALL, s.Px, off);
    r.Py = __shfl_down_sync(WALL, s.Py, off);
    r.Pz = __shfl_down_sync(WALL, s.Pz, off);
    r.T  = __shfl_down_sync(WALL, s.T,  off);
    r.G  = __shfl_down_sync(WALL, s.G,  off);
    return r;
}
// ordered warp fold: lane0 ends with combine of lanes 0..31 in order
__device__ __forceinline__ S12 warp_fold(S12 s) {
#pragma unroll
    for (int off = 1; off < 32; off <<= 1) {
        S12 o = shfl_down_S(s, off);
        s = scomb(s, o);
    }
    return s;  // valid at lane 0
}

// ---------------- double summary algebra ----------------
__device__ __forceinline__ DS dident() {
    DS d; d.dq = make_float4(0.f,0.f,0.f,1.f);
    d.Ax=d.Ay=d.Az=d.Px=d.Py=d.Pz=0.0; d.T=d.G=0.0; return d;
}
__device__ __forceinline__ DS dcomb(const DS& a, const DS& b) {
    DS o;
    o.T = a.T + b.T;
    o.G = a.G + a.T * b.T + b.G;
    double rx, ry, rz;
    qrotd(a.dq, b.Ax, b.Ay, b.Az, rx, ry, rz);
    o.Ax = a.Ax + rx;  o.Ay = a.Ay + ry;  o.Az = a.Az + rz;
    qrotd(a.dq, b.Px, b.Py, b.Pz, rx, ry, rz);
    o.Px = a.Px + a.Ax * b.T + rx;
    o.Py = a.Py + a.Ay * b.T + ry;
    o.Pz = a.Pz + a.Az * b.T + rz;
    o.dq = qnorm4(qmul4(a.dq, b.dq));
    return o;
}
__device__ __forceinline__ DS shfl_up_D(const DS& s, int off) {
    DS r;
    r.dq.x = __shfl_up_sync(WALL, s.dq.x, off);
    r.dq.y = __shfl_up_sync(WALL, s.dq.y, off);
    r.dq.z = __shfl_up_sync(WALL, s.dq.z, off);
    r.dq.w = __shfl_up_sync(WALL, s.dq.w, off);
    r.Ax = __shfl_up_sync(WALL, s.Ax, off);
    r.Ay = __shfl_up_sync(WALL, s.Ay, off);
    r.Az = __shfl_up_sync(WALL, s.Az, off);
    r.Px = __shfl_up_sync(WALL, s.Px, off);
    r.Py = __shfl_up_sync(WALL, s.Py, off);
    r.Pz = __shfl_up_sync(WALL, s.Pz, off);
    r.T  = __shfl_up_sync(WALL, s.T,  off);
    r.G  = __shfl_up_sync(WALL, s.G,  off);
    return r;
}

// ---------------- kernel 1: fused pack + per-chunk summary (warp per chunk) ----------------
__global__ void k_chunk(const float* __restrict__ acc, const float* __restrict__ gyr,
                        const float* __restrict__ ab,  const float* __restrict__ gb,
                        const float* __restrict__ dts) {
    int w    = (blockIdx.x * blockDim.x + threadIdx.x) >> 5;   // chunk id
    int lane = threadIdx.x & 31;
    float abx = __ldg(&ab[0]), aby = __ldg(&ab[1]), abz = __ldg(&ab[2]);
    float gbx = __ldg(&gb[0]), gby = __ldg(&gb[1]), gbz = __ldg(&gb[2]);
    S12 carry = sident();
#pragma unroll
    for (int it = 0; it < 4; it++) {
        int idx = (w << LOG_L) + (it << 5) + lane;
        float ax = acc[3*idx+0] - abx;
        float ay = acc[3*idx+1] - aby;
        float az = acc[3*idx+2] - abz;
        float dt = dts[idx];
        float px = (gyr[3*idx+0] - gbx) * dt;
        float py = (gyr[3*idx+1] - gby) * dt;
        float pz = (gyr[3*idx+2] - gbz) * dt;
        float th2 = px*px + py*py + pz*pz;
        float half = 0.5f * sqrtf(th2);
        float h2 = half * half;
        float sc;
        if (half > 1e-3f) sc = sinf(half) / half;
        else              sc = 1.0f - h2*(1.0f/6.0f)*(1.0f - h2*0.05f);
        float k = 0.5f * sc;
        float4 dq = make_float4(px*k, py*k, pz*k, cosf(half));
        g_dq[idx]  = dq;
        g_adt[idx] = make_float4(ax, ay, az, dt);
        S12 s;
        s.dq = dq;
        s.T  = dt;
        s.G  = 0.5f * dt * dt;
        float h = 0.5f * dt * dt;
        s.Ax = ax*dt;  s.Ay = ay*dt;  s.Az = az*dt;
        s.Px = ax*h;   s.Py = ay*h;   s.Pz = az*h;
        s = warp_fold(s);            // lane0: total of these 32 steps
        carry = (it == 0) ? s : scomb(carry, s);  // only lane0's value matters
    }
    if (lane == 0) {
        carry.dq = qnorm4(carry.dq);
        g_s0[w] = carry.dq;
        g_s1[w] = make_float4(carry.Ax, carry.Ay, carry.Az, carry.T);
        g_s2[w] = make_float4(carry.Px, carry.Py, carry.Pz, carry.G);
    }
}

// ---------------- kernel 2a: within-group inclusive scan (warp per 32 chunks, double) ----------------
__global__ void kS1() {
    int g    = (blockIdx.x * blockDim.x + threadIdx.x) >> 5;
    int lane = threadIdx.x & 31;
    int c = (g << 5) + lane;
    float4 s0 = g_s0[c], s1 = g_s1[c], s2 = g_s2[c];
    DS d;
    d.dq = s0;
    d.Ax = s1.x; d.Ay = s1.y; d.Az = s1.z; d.T = s1.w;
    d.Px = s2.x; d.Py = s2.y; d.Pz = s2.z; d.G = s2.w;
#pragma unroll
    for (int off = 1; off < 32; off <<= 1) {
        DS o = shfl_up_D(d, off);
        if (lane >= off) d = dcomb(o, d);
    }
    g_incl[c] = d;
    if (lane == 31) g_gt[g] = d;
}

// ---------------- kernel 2b: scan group totals (1 warp) ----------------
__global__ void kS2() {
    int lane = threadIdx.x;
    DS a = g_gt[2*lane];
    DS b = g_gt[2*lane+1];
    DS t = dcomb(a, b);
#pragma unroll
    for (int off = 1; off < 32; off <<= 1) {
        DS o = shfl_up_D(t, off);
        if (lane >= off) t = dcomb(o, t);
    }
    DS ex = shfl_up_D(t, 1);
    if (lane == 0) ex = dident();
    g_gp[2*lane]   = ex;
    g_gp[2*lane+1] = dcomb(ex, a);
}

// ---------------- kernel 2c: apply -> chunk-start states ----------------
__global__ void kS3(const float* __restrict__ q0p, const float* __restrict__ p0p,
                    const float* __restrict__ v0p) {
    int c = blockIdx.x * blockDim.x + threadIdx.x;
    if (c >= CC) return;
    int g = c >> 5;
    DS ex = (c & 31) ? dcomb(g_gp[g], g_incl[c-1]) : g_gp[g];
    float4 q0 = make_float4(q0p[0], q0p[1], q0p[2], q0p[3]);
    double v0x = v0p[0], v0y = v0p[1], v0z = v0p[2];
    double p0x = p0p[0], p0y = p0p[1], p0z = p0p[2];
    const double gz = -(double)GRAV;
    float4 qc = qnorm4(qmul4(q0, ex.dq));
    double rx, ry, rz;
    qrotd(q0, ex.Ax, ex.Ay, ex.Az, rx, ry, rz);
    double vx = v0x + rx, vy = v0y + ry, vz = v0z + rz + gz * ex.T;
    qrotd(q0, ex.Px, ex.Py, ex.Pz, rx, ry, rz);
    double px = p0x + v0x * ex.T + rx;
    double py = p0y + v0y * ex.T + ry;
    double pz = p0z + v0z * ex.T + rz + gz * ex.G;
    g_sq[c] = qc;
    g_sv[3*c] = vx; g_sv[3*c+1] = vy; g_sv[3*c+2] = vz;
    g_sp[3*c] = px; g_sp[3*c+1] = py; g_sp[3*c+2] = pz;
}

// ---------------- kernel 3: sync-point evaluation (warp per sync point) ----------------
__global__ void k_sync(const int* __restrict__ sync, const float* __restrict__ prot,
                       const float* __restrict__ ptrn) {
    int w    = (blockIdx.x * blockDim.x + threadIdx.x) >> 5;   // sync id
    int lane = threadIdx.x & 31;
    int i  = sync[w];
    int c  = i >> LOG_L;
    int rr = i & (LL - 1);
    int base = c << LOG_L;
    int ng = (rr >> 5) + 1;
    S12 carry = sident();
    for (int it = 0; it < ng; it++) {
        int j = (it << 5) + lane;
        S12 s;
        if (j <= rr) {
            float4 dq = g_dq[base + j];
            float4 a4 = g_adt[base + j];
            float dt = a4.w;
            float h  = 0.5f * dt * dt;
            s.dq = dq;
            s.T = dt;  s.G = h;
            s.Ax = a4.x*dt;  s.Ay = a4.y*dt;  s.Az = a4.z*dt;
            s.Px = a4.x*h;   s.Py = a4.y*h;   s.Pz = a4.z*h;
        } else {
            s = sident();
        }
        s = warp_fold(s);
        carry = (it == 0) ? s : scomb(carry, s);
    }
    if (lane == 0) {
        float4 qc = g_sq[c];
        float4 q = qnorm4(qmul4(qc, carry.dq));
        double tel = (double)carry.T;
        const double gz = -(double)GRAV;
        double rx, ry, rz;
        qrotd(qc, carry.Px, carry.Py, carry.Pz, rx, ry, rz);
        double Pxx = g_sp[3*c]   + g_sv[3*c]  * tel + rx;
        double Pyy = g_sp[3*c+1] + g_sv[3*c+1]* tel + ry;
        double Pzz = g_sp[3*c+2] + g_sv[3*c+2]* tel + rz + gz * (double)carry.G;

        float4 pq = make_float4(prot[4*w], prot[4*w+1], prot[4*w+2], prot[4*w+3]);
        float4 rel = qmul4(make_float4(-pq.x, -pq.y, -pq.z, pq.w), q);
        float nn2 = rel.x*rel.x + rel.y*rel.y + rel.z*rel.z;
        float nn = sqrtf(nn2);
        float theta = 2.0f * atan2f(nn, rel.w);
        float scale = (nn < 1e-7f) ? 2.0f : theta / fmaxf(nn, 1e-12f);
        double lsq = (double)(nn2 * scale * scale);

        float dx = ptrn[3*w+0] - (float)Pxx;
        float dy = ptrn[3*w+1] - (float)Pyy;
        float dz = ptrn[3*w+2] - (float)Pzz;
        g_part[w]      = lsq;
        g_part[MM + w] = (double)dx*dx + (double)dy*dy + (double)dz*dz;
    }
}

// ---------------- kernel 4: deterministic reduction ----------------
__global__ void k_reduce(float* __restrict__ out) {
    __shared__ double s1[1024];
    __shared__ double s2[1024];
    int t = threadIdx.x;
    s1[t] = g_part[t] + g_part[t + 1024];
    s2[t] = g_part[2048 + t] + g_part[3072 + t];
    __syncthreads();
    for (int off = 512; off > 0; off >>= 1) {
        if (t < off) { s1[t] += s1[t + off]; s2[t] += s2[t + off]; }
        __syncthreads();
    }
    if (t == 0) out[0] = (float)(sqrt(s1[0]) + s2[0] / (3.0 * (double)MM));
}

// ---------------- launch ----------------
extern "C" void kernel_launch(void* const* d_in, const int* in_sizes, int n_in,
                              void* d_out, int out_size) {
    const float* acc  = (const float*)d_in[0];
    const float* gyr  = (const float*)d_in[1];
    const float* ab   = (const float*)d_in[2];
    const float* gb   = (const float*)d_in[3];
    const float* dts  = (const float*)d_in[4];
    const float* q0   = (const float*)d_in[5];
    const float* p0   = (const float*)d_in[6];
    const float* v0   = (const float*)d_in[7];
    const float* prot = (const float*)d_in[8];
    const float* ptrn = (const float*)d_in[9];
    const int*   sync = (const int*)d_in[10];

    k_chunk <<<CC*32/256, 256>>>(acc, gyr, ab, gb, dts);   // 256 blocks, warp/chunk
    kS1     <<<GG*32/256, 256>>>();                        // 8 blocks
    kS2     <<<1, 32>>>();
    kS3     <<<CC/256, 256>>>(q0, p0, v0);
    k_sync  <<<MM*32/256, 256>>>(sync, prot, ptrn);        // 256 blocks, warp/sync
    k_reduce<<<1, 1024>>>((float*)d_out);
}

// round 4
// speedup vs baseline: 2.3773x; 2.3773x over previous
#include <cuda_runtime.h>
#include <math.h>

#define NN 262144
#define LL 128
#define LOG_L 7
#define CC (NN / LL)      // 2048 chunks
#define MM 2048
#define GRAV 9.81007f

struct S12 { float4 dq; float Ax,Ay,Az,Px,Py,Pz,T,G; };

__device__ float4 g_s0[CC];     // chunk summary: dq
__device__ float4 g_s1[CC];     // Ax,Ay,Az,T
__device__ float4 g_s2[CC];     // Px,Py,Pz,G
__device__ float4 g_sq[CC];     // chunk-start world rotation
__device__ float  g_sv[3 * CC]; // chunk-start world velocity
__device__ float  g_sp[3 * CC]; // chunk-start world position
__device__ double g_part[2 * MM];

// ---------------- quaternion helpers ----------------
__device__ __forceinline__ float4 qmul4(float4 q, float4 r) {
    return make_float4(
        q.w*r.x + q.x*r.w + q.y*r.z - q.z*r.y,
        q.w*r.y - q.x*r.z + q.y*r.w + q.z*r.x,
        q.w*r.z + q.x*r.y - q.y*r.x + q.z*r.w,
        q.w*r.w - q.x*r.x - q.y*r.y - q.z*r.z);
}
__device__ __forceinline__ float4 qnorm4(float4 q) {
    float n = rsqrtf(q.x*q.x + q.y*q.y + q.z*q.z + q.w*q.w);
    return make_float4(q.x*n, q.y*n, q.z*n, q.w*n);
}
__device__ __forceinline__ float3 qrot3(float4 q, float3 v) {
    float tx = 2.0f*(q.y*v.z - q.z*v.y);
    float ty = 2.0f*(q.z*v.x - q.x*v.z);
    float tz = 2.0f*(q.x*v.y - q.y*v.x);
    return make_float3(
        v.x + q.w*tx + (q.y*tz - q.z*ty),
        v.y + q.w*ty + (q.z*tx - q.x*tz),
        v.z + q.w*tz + (q.x*ty - q.y*tx));
}

// ---------------- summary algebra (float) ----------------
__device__ __forceinline__ S12 sident() {
    S12 s; s.dq = make_float4(0.f,0.f,0.f,1.f);
    s.Ax=s.Ay=s.Az=s.Px=s.Py=s.Pz=0.f; s.T=s.G=0.f; return s;
}
__device__ __forceinline__ S12 scomb(const S12& a, const S12& b) {
    S12 o;
    o.T = a.T + b.T;
    o.G = a.G + a.T*b.T + b.G;
    float3 rA = qrot3(a.dq, make_float3(b.Ax, b.Ay, b.Az));
    o.Ax = a.Ax + rA.x;  o.Ay = a.Ay + rA.y;  o.Az = a.Az + rA.z;
    float3 rP = qrot3(a.dq, make_float3(b.Px, b.Py, b.Pz));
    o.Px = a.Px + a.Ax*b.T + rP.x;
    o.Py = a.Py + a.Ay*b.T + rP.y;
    o.Pz = a.Pz + a.Az*b.T + rP.z;
    o.dq = qmul4(a.dq, b.dq);
    return o;
}
#define WALL 0xffffffffu
__device__ __forceinline__ S12 shfl_down_S(const S12& s, int off) {
    S12 r;
    r.dq.x = __shfl_down_sync(WALL, s.dq.x, off);
    r.dq.y = __shfl_down_sync(WALL, s.dq.y, off);
    r.dq.z = __shfl_down_sync(WALL, s.dq.z, off);
    r.dq.w = __shfl_down_sync(WALL, s.dq.w, off);
    r.Ax = __shfl_down_sync(WALL, s.Ax, off);
    r.Ay = __shfl_down_sync(WALL, s.Ay, off);
    r.Az = __shfl_down_sync(WALL, s.Az, off);
    r.Px = __shfl_down_sync(WALL, s.Px, off);
    r.Py = __shfl_down_sync(WALL, s.Py, off);
    r.Pz = __shfl_down_sync(WALL, s.Pz, off);
    r.T  = __shfl_down_sync(WALL, s.T,  off);
    r.G  = __shfl_down_sync(WALL, s.G,  off);
    return r;
}
__device__ __forceinline__ S12 shfl_up_S(const S12& s, int off) {
    S12 r;
    r.dq.x = __shfl_up_sync(WALL, s.dq.x, off);
    r.dq.y = __shfl_up_sync(WALL, s.dq.y, off);
    r.dq.z = __shfl_up_sync(WALL, s.dq.z, off);
    r.dq.w = __shfl_up_sync(WALL, s.dq.w, off);
    r.Ax = __shfl_up_sync(WALL, s.Ax, off);
    r.Ay = __shfl_up_sync(WALL, s.Ay, off);
    r.Az = __shfl_up_sync(WALL, s.Az, off);
    r.Px = __shfl_up_sync(WALL, s.Px, off);
    r.Py = __shfl_up_sync(WALL, s.Py, off);
    r.Pz = __shfl_up_sync(WALL, s.Pz, off);
    r.T  = __shfl_up_sync(WALL, s.T,  off);
    r.G  = __shfl_up_sync(WALL, s.G,  off);
    return r;
}
// ordered fold: lane0 ends with combine of lanes 0..31 in order
__device__ __forceinline__ S12 warp_fold(S12 s) {
#pragma unroll
    for (int off = 1; off < 32; off <<= 1) {
        S12 o = shfl_down_S(s, off);
        s = scomb(s, o);
    }
    return s;
}
// inclusive ordered scan across lanes
__device__ __forceinline__ S12 warp_scan(S12 s, int lane) {
#pragma unroll
    for (int off = 1; off < 32; off <<= 1) {
        S12 o = shfl_up_S(s, off);
        if (lane >= off) s = scomb(o, s);
    }
    return s;
}

// per-step local summary from raw inputs
__device__ __forceinline__ S12 step_summ(const float* __restrict__ acc,
                                         const float* __restrict__ gyr,
                                         const float* __restrict__ dts,
                                         float abx, float aby, float abz,
                                         float gbx, float gby, float gbz, int idx) {
    float ax = acc[3*idx+0] - abx;
    float ay = acc[3*idx+1] - aby;
    float az = acc[3*idx+2] - abz;
    float dt = dts[idx];
    float px = (gyr[3*idx+0] - gbx) * dt;
    float py = (gyr[3*idx+1] - gby) * dt;
    float pz = (gyr[3*idx+2] - gbz) * dt;
    float th2 = px*px + py*py + pz*pz;
    float half = 0.5f * sqrtf(th2);
    float h2 = half * half;
    float sc;
    if (half > 1e-3f) sc = sinf(half) / half;
    else              sc = 1.0f - h2*(1.0f/6.0f)*(1.0f - h2*0.05f);
    float k = 0.5f * sc;
    S12 s;
    s.dq = make_float4(px*k, py*k, pz*k, cosf(half));
    float h = 0.5f * dt * dt;
    s.T  = dt;  s.G = h;
    s.Ax = ax*dt;  s.Ay = ay*dt;  s.Az = az*dt;
    s.Px = ax*h;   s.Py = ay*h;   s.Pz = az*h;
    return s;
}

// ---------------- kernel 1: per-chunk summaries (warp/chunk, serial-4 per lane) ----------------
__global__ void k_chunk(const float* __restrict__ acc, const float* __restrict__ gyr,
                        const float* __restrict__ ab,  const float* __restrict__ gb,
                        const float* __restrict__ dts) {
    int w    = (blockIdx.x * blockDim.x + threadIdx.x) >> 5;   // chunk id
    int lane = threadIdx.x & 31;
    float abx = __ldg(&ab[0]), aby = __ldg(&ab[1]), abz = __ldg(&ab[2]);
    float gbx = __ldg(&gb[0]), gby = __ldg(&gb[1]), gbz = __ldg(&gb[2]);
    int base = (w << LOG_L) + (lane << 2);
    S12 s = step_summ(acc, gyr, dts, abx,aby,abz, gbx,gby,gbz, base);
#pragma unroll
    for (int k = 1; k < 4; k++)
        s = scomb(s, step_summ(acc, gyr, dts, abx,aby,abz, gbx,gby,gbz, base + k));
    s = warp_fold(s);
    if (lane == 0) {
        s.dq = qnorm4(s.dq);
        g_s0[w] = s.dq;
        g_s1[w] = make_float4(s.Ax, s.Ay, s.Az, s.T);
        g_s2[w] = make_float4(s.Px, s.Py, s.Pz, s.G);
    }
}

// ---------------- kernel 2: fused block-level scan -> chunk-start states ----------------
__global__ void k_scan(const float* __restrict__ q0p, const float* __restrict__ p0p,
                       const float* __restrict__ v0p) {
    __shared__ S12 shw[32];
    int t = threadIdx.x, lane = t & 31, wid = t >> 5;
    // load this thread's 2 chunks
    int c0 = 2*t;
    float4 a0 = g_s0[c0],   a1 = g_s1[c0],   a2 = g_s2[c0];
    float4 b0 = g_s0[c0+1], b1 = g_s1[c0+1], b2 = g_s2[c0+1];
    S12 a; a.dq=a0; a.Ax=a1.x; a.Ay=a1.y; a.Az=a1.z; a.T=a1.w; a.Px=a2.x; a.Py=a2.y; a.Pz=a2.z; a.G=a2.w;
    S12 b; b.dq=b0; b.Ax=b1.x; b.Ay=b1.y; b.Az=b1.z; b.T=b1.w; b.Px=b2.x; b.Py=b2.y; b.Pz=b2.z; b.G=b2.w;
    S12 tot = scomb(a, b);
    S12 inc = warp_scan(tot, lane);
    if (lane == 31) shw[wid] = inc;
    __syncthreads();
    if (wid == 0) {
        S12 v = shw[lane];
        v = warp_scan(v, lane);
        shw[lane] = v;
    }
    __syncthreads();
    S12 lex = shfl_up_S(inc, 1);        // lane-exclusive (valid lane>0)
    S12 ex;
    if (wid == 0) ex = (lane == 0) ? sident() : lex;
    else          ex = (lane == 0) ? shw[wid-1] : scomb(shw[wid-1], lex);

    float4 q0 = make_float4(q0p[0], q0p[1], q0p[2], q0p[3]);
    float3 v0 = make_float3(v0p[0], v0p[1], v0p[2]);
    float3 p0 = make_float3(p0p[0], p0p[1], p0p[2]);
#pragma unroll
    for (int k = 0; k < 2; k++) {
        int c = c0 + k;
        float4 qc = qnorm4(qmul4(q0, ex.dq));
        float3 rA = qrot3(q0, make_float3(ex.Ax, ex.Ay, ex.Az));
        float3 rP = qrot3(q0, make_float3(ex.Px, ex.Py, ex.Pz));
        g_sq[c] = qc;
        g_sv[3*c]   = v0.x + rA.x;
        g_sv[3*c+1] = v0.y + rA.y;
        g_sv[3*c+2] = v0.z + rA.z - GRAV * ex.T;
        g_sp[3*c]   = p0.x + v0.x * ex.T + rP.x;
        g_sp[3*c+1] = p0.y + v0.y * ex.T + rP.y;
        g_sp[3*c+2] = p0.z + v0.z * ex.T + rP.z - GRAV * ex.G;
        if (k == 0) ex = scomb(ex, a);
    }
}

// ---------------- kernel 3: sync-point evaluation (warp/sync, serial-4 masked) ----------------
__global__ void k_sync(const int* __restrict__ sync, const float* __restrict__ prot,
                       const float* __restrict__ ptrn,
                       const float* __restrict__ acc, const float* __restrict__ gyr,
                       const float* __restrict__ ab,  const float* __restrict__ gb,
                       const float* __restrict__ dts) {
    int w    = (blockIdx.x * blockDim.x + threadIdx.x) >> 5;   // sync id
    int lane = threadIdx.x & 31;
    int i  = sync[w];
    int c  = i >> LOG_L;
    int rr = i & (LL - 1);
    float abx = __ldg(&ab[0]), aby = __ldg(&ab[1]), abz = __ldg(&ab[2]);
    float gbx = __ldg(&gb[0]), gby = __ldg(&gb[1]), gbz = __ldg(&gb[2]);
    int base = (c << LOG_L) + (lane << 2);
    S12 s = sident();
#pragma unroll
    for (int k = 0; k < 4; k++) {
        if ((lane << 2) + k <= rr)
            s = scomb(s, step_summ(acc, gyr, dts, abx,aby,abz, gbx,gby,gbz, base + k));
    }
    s = warp_fold(s);
    if (lane == 0) {
        float4 qc = g_sq[c];
        float4 q = qnorm4(qmul4(qc, s.dq));
        float tel = s.T;
        float3 rP = qrot3(qc, make_float3(s.Px, s.Py, s.Pz));
        float Pxx = g_sp[3*c]   + g_sv[3*c]  * tel + rP.x;
        float Pyy = g_sp[3*c+1] + g_sv[3*c+1]* tel + rP.y;
        float Pzz = g_sp[3*c+2] + g_sv[3*c+2]* tel + rP.z - GRAV * s.G;

        float4 pq = make_float4(prot[4*w], prot[4*w+1], prot[4*w+2], prot[4*w+3]);
        float4 rel = qmul4(make_float4(-pq.x, -pq.y, -pq.z, pq.w), q);
        float nn2 = rel.x*rel.x + rel.y*rel.y + rel.z*rel.z;
        float nn = sqrtf(nn2);
        float theta = 2.0f * atan2f(nn, rel.w);
        float scale = (nn < 1e-7f) ? 2.0f : theta / fmaxf(nn, 1e-12f);
        float lsq = nn2 * scale * scale;

        float dx = ptrn[3*w+0] - Pxx;
        float dy = ptrn[3*w+1] - Pyy;
        float dz = ptrn[3*w+2] - Pzz;
        g_part[w]      = (double)lsq;
        g_part[MM + w] = (double)dx*dx + (double)dy*dy + (double)dz*dz;
    }
}

// ---------------- kernel 4: deterministic reduction ----------------
__global__ void k_reduce(float* __restrict__ out) {
    __shared__ double s1[1024];
    __shared__ double s2[1024];
    int t = threadIdx.x;
    s1[t] = g_part[t] + g_part[t + 1024];
    s2[t] = g_part[2048 + t] + g_part[3072 + t];
    __syncthreads();
    for (int off = 512; off > 0; off >>= 1) {
        if (t < off) { s1[t] += s1[t + off]; s2[t] += s2[t + off]; }
        __syncthreads();
    }
    if (t == 0) out[0] = (float)(sqrt(s1[0]) + s2[0] / (3.0 * (double)MM));
}

// ---------------- launch ----------------
extern "C" void kernel_launch(void* const* d_in, const int* in_sizes, int n_in,
                              void* d_out, int out_size) {
    const float* acc  = (const float*)d_in[0];
    const float* gyr  = (const float*)d_in[1];
    const float* ab   = (const float*)d_in[2];
    const float* gb   = (const float*)d_in[3];
    const float* dts  = (const float*)d_in[4];
    const float* q0   = (const float*)d_in[5];
    const float* p0   = (const float*)d_in[6];
    const float* v0   = (const float*)d_in[7];
    const float* prot = (const float*)d_in[8];
    const float* ptrn = (const float*)d_in[9];
    const int*   sync = (const int*)d_in[10];

    k_chunk <<<CC*32/256, 256>>>(acc, gyr, ab, gb, dts);
    k_scan  <<<1, 1024>>>(q0, p0, v0);
    k_sync  <<<MM*32/256, 256>>>(sync, prot, ptrn, acc, gyr, ab, gb, dts);
    k_reduce<<<1, 1024>>>((float*)d_out);
}

// round 5
// speedup vs baseline: 2.9127x; 1.2252x over previous
#include <cuda_runtime.h>
#include <math.h>

#define NN 262144
#define LL 128
#define LOG_L 7
#define CC (NN / LL)      // 2048 chunks
#define MM 2048
#define GRAV 9.81007f
#define WALL 0xffffffffu

struct S12 { float4 dq; float Ax,Ay,Az,Px,Py,Pz,T,G; };

__device__ float4 g_s0[CC];      // chunk totals: dq
__device__ float4 g_s1[CC];      // Ax,Ay,Az,T
__device__ float4 g_s2[CC];      // Px,Py,Pz,G
__device__ float4 g_b0[3 * CC];  // sub-prefixes (32/64/96 steps): dq
__device__ float4 g_b1[3 * CC];  // Ax,Ay,Az,T
__device__ float4 g_b2[3 * CC];  // Px,Py,Pz,G
__device__ float4 g_sq[CC];      // chunk-start world rotation
__device__ float  g_sv[3 * CC];
__device__ float  g_sp[3 * CC];
__device__ double g_part[2 * MM];
__device__ unsigned g_ctr = 0;

// ---------------- quaternion helpers ----------------
__device__ __forceinline__ float4 qmul4(float4 q, float4 r) {
    return make_float4(
        q.w*r.x + q.x*r.w + q.y*r.z - q.z*r.y,
        q.w*r.y - q.x*r.z + q.y*r.w + q.z*r.x,
        q.w*r.z + q.x*r.y - q.y*r.x + q.z*r.w,
        q.w*r.w - q.x*r.x - q.y*r.y - q.z*r.z);
}
__device__ __forceinline__ float4 qnorm4(float4 q) {
    float n = rsqrtf(q.x*q.x + q.y*q.y + q.z*q.z + q.w*q.w);
    return make_float4(q.x*n, q.y*n, q.z*n, q.w*n);
}
__device__ __forceinline__ float3 qrot3(float4 q, float3 v) {
    float tx = 2.0f*(q.y*v.z - q.z*v.y);
    float ty = 2.0f*(q.z*v.x - q.x*v.z);
    float tz = 2.0f*(q.x*v.y - q.y*v.x);
    return make_float3(
        v.x + q.w*tx + (q.y*tz - q.z*ty),
        v.y + q.w*ty + (q.z*tx - q.x*tz),
        v.z + q.w*tz + (q.x*ty - q.y*tx));
}

// ---------------- summary algebra ----------------
__device__ __forceinline__ S12 sident() {
    S12 s; s.dq = make_float4(0.f,0.f,0.f,1.f);
    s.Ax=s.Ay=s.Az=s.Px=s.Py=s.Pz=0.f; s.T=s.G=0.f; return s;
}
__device__ __forceinline__ S12 scomb(const S12& a, const S12& b) {
    S12 o;
    o.T = a.T + b.T;
    o.G = a.G + a.T*b.T + b.G;
    float3 rA = qrot3(a.dq, make_float3(b.Ax, b.Ay, b.Az));
    o.Ax = a.Ax + rA.x;  o.Ay = a.Ay + rA.y;  o.Az = a.Az + rA.z;
    float3 rP = qrot3(a.dq, make_float3(b.Px, b.Py, b.Pz));
    o.Px = a.Px + a.Ax*b.T + rP.x;
    o.Py = a.Py + a.Ay*b.T + rP.y;
    o.Pz = a.Pz + a.Az*b.T + rP.z;
    o.dq = qmul4(a.dq, b.dq);
    return o;
}
__device__ __forceinline__ S12 shfl_down_S(const S12& s, int off) {
    S12 r;
    r.dq.x = __shfl_down_sync(WALL, s.dq.x, off);
    r.dq.y = __shfl_down_sync(WALL, s.dq.y, off);
    r.dq.z = __shfl_down_sync(WALL, s.dq.z, off);
    r.dq.w = __shfl_down_sync(WALL, s.dq.w, off);
    r.Ax = __shfl_down_sync(WALL, s.Ax, off);
    r.Ay = __shfl_down_sync(WALL, s.Ay, off);
    r.Az = __shfl_down_sync(WALL, s.Az, off);
    r.Px = __shfl_down_sync(WALL, s.Px, off);
    r.Py = __shfl_down_sync(WALL, s.Py, off);
    r.Pz = __shfl_down_sync(WALL, s.Pz, off);
    r.T  = __shfl_down_sync(WALL, s.T,  off);
    r.G  = __shfl_down_sync(WALL, s.G,  off);
    return r;
}
__device__ __forceinline__ S12 shfl_up_S(const S12& s, int off) {
    S12 r;
    r.dq.x = __shfl_up_sync(WALL, s.dq.x, off);
    r.dq.y = __shfl_up_sync(WALL, s.dq.y, off);
    r.dq.z = __shfl_up_sync(WALL, s.dq.z, off);
    r.dq.w = __shfl_up_sync(WALL, s.dq.w, off);
    r.Ax = __shfl_up_sync(WALL, s.Ax, off);
    r.Ay = __shfl_up_sync(WALL, s.Ay, off);
    r.Az = __shfl_up_sync(WALL, s.Az, off);
    r.Px = __shfl_up_sync(WALL, s.Px, off);
    r.Py = __shfl_up_sync(WALL, s.Py, off);
    r.Pz = __shfl_up_sync(WALL, s.Pz, off);
    r.T  = __shfl_up_sync(WALL, s.T,  off);
    r.G  = __shfl_up_sync(WALL, s.G,  off);
    return r;
}
__device__ __forceinline__ S12 warp_fold(S12 s) {
#pragma unroll
    for (int off = 1; off < 32; off <<= 1) s = scomb(s, shfl_down_S(s, off));
    return s;  // lane 0
}
__device__ __forceinline__ S12 warp_scan(S12 s, int lane) {
#pragma unroll
    for (int off = 1; off < 32; off <<= 1) {
        S12 o = shfl_up_S(s, off);
        if (lane >= off) s = scomb(o, s);
    }
    return s;
}

// per-step summary from registers (Taylor exp_so3; guarded libm fallback)
__device__ __forceinline__ S12 step_reg(float ax, float ay, float az,
                                        float gx, float gy, float gz, float dt,
                                        float abx, float aby, float abz,
                                        float gbx, float gby, float gbz) {
    ax -= abx; ay -= aby; az -= abz;
    float px = (gx - gbx) * dt;
    float py = (gy - gby) * dt;
    float pz = (gz - gbz) * dt;
    float th2 = px*px + py*py + pz*pz;
    float h2 = 0.25f * th2;                  // half^2
    float sc, w;
    if (h2 < 0.04f) {                        // half < 0.2 rad: always in practice
        sc = 1.0f - h2*(1.0f/6.0f)*(1.0f - h2*0.05f);
        w  = 1.0f - h2*0.5f*(1.0f - h2*(1.0f/12.0f));
    } else {
        float half = sqrtf(h2);
        sc = sinf(half) / half;
        w  = cosf(half);
    }
    float k = 0.5f * sc;
    S12 s;
    s.dq = make_float4(px*k, py*k, pz*k, w);
    float h = 0.5f * dt * dt;
    s.T = dt;  s.G = h;
    s.Ax = ax*dt;  s.Ay = ay*dt;  s.Az = az*dt;
    s.Px = ax*h;   s.Py = ay*h;   s.Pz = az*h;
    return s;
}

// ---------------- kernel 1: chunk summaries + sub-prefixes ----------------
__global__ void k_chunk(const float* __restrict__ acc, const float* __restrict__ gyr,
                        const float* __restrict__ ab,  const float* __restrict__ gb,
                        const float* __restrict__ dts) {
    int w    = (blockIdx.x * blockDim.x + threadIdx.x) >> 5;   // chunk id
    int lane = threadIdx.x & 31;
    float abx = __ldg(&ab[0]), aby = __ldg(&ab[1]), abz = __ldg(&ab[2]);
    float gbx = __ldg(&gb[0]), gby = __ldg(&gb[1]), gbz = __ldg(&gb[2]);
    const float4* acc4 = (const float4*)acc;
    const float4* gyr4 = (const float4*)gyr;
    const float4* dt4  = (const float4*)dts;
    int vb = 96*w + 3*lane;
    float4 A0 = acc4[vb], A1 = acc4[vb+1], A2 = acc4[vb+2];
    float4 G0 = gyr4[vb], G1 = gyr4[vb+1], G2 = gyr4[vb+2];
    float4 D  = dt4[(w<<5) + lane];
    S12 s =      step_reg(A0.x,A0.y,A0.z, G0.x,G0.y,G0.z, D.x, abx,aby,abz, gbx,gby,gbz);
    s = scomb(s, step_reg(A0.w,A1.x,A1.y, G0.w,G1.x,G1.y, D.y, abx,aby,abz, gbx,gby,gbz));
    s = scomb(s, step_reg(A1.z,A1.w,A2.x, G1.z,G1.w,G2.x, D.z, abx,aby,abz, gbx,gby,gbz));
    s = scomb(s, step_reg(A2.y,A2.z,A2.w, G2.y,G2.z,G2.w, D.w, abx,aby,abz, gbx,gby,gbz));
    s = warp_scan(s, lane);    // inclusive prefix at 4-step boundaries
    if ((lane & 7) == 7 && lane != 31) {
        int sub = lane >> 3;   // 0,1,2 -> after 32/64/96 steps
        g_b0[3*w + sub] = s.dq;
        g_b1[3*w + sub] = make_float4(s.Ax, s.Ay, s.Az, s.T);
        g_b2[3*w + sub] = make_float4(s.Px, s.Py, s.Pz, s.G);
    }
    if (lane == 31) {
        s.dq = qnorm4(s.dq);
        g_s0[w] = s.dq;
        g_s1[w] = make_float4(s.Ax, s.Ay, s.Az, s.T);
        g_s2[w] = make_float4(s.Px, s.Py, s.Pz, s.G);
    }
}

// ---------------- kernel 2: block-level scan -> chunk-start states ----------------
__global__ void k_scan(const float* __restrict__ q0p, const float* __restrict__ p0p,
                       const float* __restrict__ v0p) {
    __shared__ S12 shw[32];
    int t = threadIdx.x, lane = t & 31, wid = t >> 5;
    if (t == 0) g_ctr = 0;                     // reset last-block counter for k_sync
    int c0 = 2*t;
    float4 a0 = g_s0[c0],   a1 = g_s1[c0],   a2 = g_s2[c0];
    float4 b0 = g_s0[c0+1], b1 = g_s1[c0+1], b2 = g_s2[c0+1];
    S12 a; a.dq=a0; a.Ax=a1.x; a.Ay=a1.y; a.Az=a1.z; a.T=a1.w; a.Px=a2.x; a.Py=a2.y; a.Pz=a2.z; a.G=a2.w;
    S12 b; b.dq=b0; b.Ax=b1.x; b.Ay=b1.y; b.Az=b1.z; b.T=b1.w; b.Px=b2.x; b.Py=b2.y; b.Pz=b2.z; b.G=b2.w;
    S12 tot = scomb(a, b);
    S12 inc = warp_scan(tot, lane);
    if (lane == 31) shw[wid] = inc;
    __syncthreads();
    if (wid == 0) shw[lane] = warp_scan(shw[lane], lane);
    __syncthreads();
    S12 lex = shfl_up_S(inc, 1);
    S12 ex;
    if (wid == 0) ex = (lane == 0) ? sident() : lex;
    else          ex = (lane == 0) ? shw[wid-1] : scomb(shw[wid-1], lex);

    float4 q0 = make_float4(q0p[0], q0p[1], q0p[2], q0p[3]);
    float3 v0 = make_float3(v0p[0], v0p[1], v0p[2]);
    float3 p0 = make_float3(p0p[0], p0p[1], p0p[2]);
#pragma unroll
    for (int k = 0; k < 2; k++) {
        int c = c0 + k;
        float4 qc = qnorm4(qmul4(q0, ex.dq));
        float3 rA = qrot3(q0, make_float3(ex.Ax, ex.Ay, ex.Az));
        float3 rP = qrot3(q0, make_float3(ex.Px, ex.Py, ex.Pz));
        g_sq[c] = qc;
        g_sv[3*c]   = v0.x + rA.x;
        g_sv[3*c+1] = v0.y + rA.y;
        g_sv[3*c+2] = v0.z + rA.z - GRAV * ex.T;
        g_sp[3*c]   = p0.x + v0.x * ex.T + rP.x;
        g_sp[3*c+1] = p0.y + v0.y * ex.T + rP.y;
        g_sp[3*c+2] = p0.z + v0.z * ex.T + rP.z - GRAV * ex.G;
        if (k == 0) ex = scomb(ex, a);
    }
}

// ---------------- kernel 3: sync eval + fused deterministic reduction ----------------
__global__ void k_sync(const int* __restrict__ sync, const float* __restrict__ prot,
                       const float* __restrict__ ptrn,
                       const float* __restrict__ acc, const float* __restrict__ gyr,
                       const float* __restrict__ ab,  const float* __restrict__ gb,
                       const float* __restrict__ dts, float* __restrict__ out) {
    __shared__ double red1[8], red2[8];
    __shared__ bool is_last;
    int w    = (blockIdx.x * blockDim.x + threadIdx.x) >> 5;   // sync id
    int lane = threadIdx.x & 31;
    int i   = sync[w];
    int c   = i >> LOG_L;
    int r   = i & (LL - 1);
    int sub = r >> 5;          // full 32-step sub-blocks before residual
    int rem = r & 31;
    float abx = __ldg(&ab[0]), aby = __ldg(&ab[1]), abz = __ldg(&ab[2]);
    float gbx = __ldg(&gb[0]), gby = __ldg(&gb[1]), gbz = __ldg(&gb[2]);
    int idx = (c << LOG_L) + (sub << 5) + lane;
    S12 s;
    if (lane <= rem) {
        s = step_reg(acc[3*idx], acc[3*idx+1], acc[3*idx+2],
                     gyr[3*idx], gyr[3*idx+1], gyr[3*idx+2], dts[idx],
                     abx,aby,abz, gbx,gby,gbz);
    } else s = sident();
    s = warp_fold(s);
    if (lane == 0) {
        if (sub > 0) {
            float4 p0 = g_b0[3*c + sub - 1];
            float4 p1 = g_b1[3*c + sub - 1];
            float4 p2 = g_b2[3*c + sub - 1];
            S12 pre; pre.dq=p0; pre.Ax=p1.x; pre.Ay=p1.y; pre.Az=p1.z; pre.T=p1.w;
            pre.Px=p2.x; pre.Py=p2.y; pre.Pz=p2.z; pre.G=p2.w;
            s = scomb(pre, s);
        }
        float4 qc = g_sq[c];
        float4 q = qnorm4(qmul4(qc, s.dq));
        float tel = s.T;
        float3 rP = qrot3(qc, make_float3(s.Px, s.Py, s.Pz));
        float Pxx = g_sp[3*c]   + g_sv[3*c]  * tel + rP.x;
        float Pyy = g_sp[3*c+1] + g_sv[3*c+1]* tel + rP.y;
        float Pzz = g_sp[3*c+2] + g_sv[3*c+2]* tel + rP.z - GRAV * s.G;

        float4 pq = make_float4(prot[4*w], prot[4*w+1], prot[4*w+2], prot[4*w+3]);
        float4 rel = qmul4(make_float4(-pq.x, -pq.y, -pq.z, pq.w), q);
        float nn2 = rel.x*rel.x + rel.y*rel.y + rel.z*rel.z;
        float nn = sqrtf(nn2);
        float theta = 2.0f * atan2f(nn, rel.w);
        float scale = (nn < 1e-7f) ? 2.0f : theta / fmaxf(nn, 1e-12f);
        float lsq = nn2 * scale * scale;

        float dx = ptrn[3*w+0] - Pxx;
        float dy = ptrn[3*w+1] - Pyy;
        float dz = ptrn[3*w+2] - Pzz;
        g_part[w]      = (double)lsq;
        g_part[MM + w] = (double)dx*dx + (double)dy*dy + (double)dz*dz;
    }
    // ---- last-block fused reduction ----
    __syncthreads();
    if (threadIdx.x == 0) {
        __threadfence();
        unsigned old = atomicAdd(&g_ctr, 1u);
        is_last = (old == gridDim.x - 1);
    }
    __syncthreads();
    if (!is_last) return;
    int t = threadIdx.x;
    double s1 = 0.0, s2 = 0.0;
#pragma unroll
    for (int k = 0; k < 8; k++) {
        s1 += g_part[t + 256*k];
        s2 += g_part[MM + t + 256*k];
    }
#pragma unroll
    for (int off = 16; off > 0; off >>= 1) {
        s1 += __shfl_down_sync(WALL, s1, off);
        s2 += __shfl_down_sync(WALL, s2, off);
    }
    if ((t & 31) == 0) { red1[t>>5] = s1; red2[t>>5] = s2; }
    __syncthreads();
    if (t == 0) {
        double a = 0.0, b = 0.0;
#pragma unroll
        for (int k = 0; k < 8; k++) { a += red1[k]; b += red2[k]; }
        out[0] = (float)(sqrt(a) + b / (3.0 * (double)MM));
    }
}

// ---------------- launch ----------------
extern "C" void kernel_launch(void* const* d_in, const int* in_sizes, int n_in,
                              void* d_out, int out_size) {
    const float* acc  = (const float*)d_in[0];
    const float* gyr  = (const float*)d_in[1];
    const float* ab   = (const float*)d_in[2];
    const float* gb   = (const float*)d_in[3];
    const float* dts  = (const float*)d_in[4];
    const float* q0   = (const float*)d_in[5];
    const float* p0   = (const float*)d_in[6];
    const float* v0   = (const float*)d_in[7];
    const float* prot = (const float*)d_in[8];
    const float* ptrn = (const float*)d_in[9];
    const int*   sync = (const int*)d_in[10];

    k_chunk <<<CC*32/256, 256>>>(acc, gyr, ab, gb, dts);
    k_scan  <<<1, 1024>>>(q0, p0, v0);
    k_sync  <<<MM*32/256, 256>>>(sync, prot, ptrn, acc, gyr, ab, gb, dts, (float*)d_out);
}